// round 2
// baseline (speedup 1.0000x reference)
#include <cuda_runtime.h>

#define T_SIM 100
#define NB 32
// e^{-1/tau}, tau = 10
#define R_DEC 0.9048374180359595f
// e/tau
#define C_EPS 0.2718281828459045f

// ---------------- scratch (device globals; no allocation allowed) -------------
__device__ float g_S0 [T_SIM * NB * 784];          // spikes in   [t][b][28][28]
__device__ float g_U1 [T_SIM * NB * 16 * 784];     // conv1 out -> spikes (in place)
__device__ float g_S1p[T_SIM * NB * 16 * 196];     // pool1+psp+spike
__device__ float g_U2 [T_SIM * NB * 32 * 196];     // conv2 out -> spikes (in place)
__device__ float g_S2p[T_SIM * NB * 1568];         // pool2+psp+spike  (A matrix of fc1)
__device__ float g_U3 [T_SIM * NB * 410];          // fc1 out -> spikes (in place)
__device__ float g_U4 [T_SIM * NB * 10];           // fc2 out (psp+spike fused in final)
__device__ float g_W1R[400];                        // w1 reordered [kq][oc]
__device__ float g_W2R[12800];                      // w2 reordered [ci*25+kq][oc]

// ---------------- encode: bernoulli spikes + transpose to time-major ----------
__global__ void k_encode(const float* __restrict__ rand_u, const float* __restrict__ img) {
    int i = blockIdx.x * blockDim.x + threadIdx.x;
    if (i >= T_SIM * NB * 784) return;
    int bp = i / T_SIM;                 // (b,y,x) flat
    int t  = i - bp * T_SIM;
    float s = (rand_u[i] < img[bp]) ? 1.0f : 0.0f;
    g_S0[t * (NB * 784) + bp] = s;
}

// ---------------- weight reorder (oc innermost for vector loads) --------------
__global__ void k_reorder(const float* __restrict__ w1, const float* __restrict__ w2) {
    int i = blockIdx.x * blockDim.x + threadIdx.x;
    if (i < 400) {
        int oc = i & 15, kq = i >> 4;
        g_W1R[i] = w1[oc * 25 + kq];
    }
    if (i < 12800) {
        int oc = i & 31, kk = i >> 5;
        int ci = kk / 25, kq = kk % 25;
        g_W2R[i] = w2[(oc * 16 + ci) * 25 + kq];
    }
}

// ---------------- conv1: 1->16ch, 28x28, 5x5 pad2, per (t,b) plane -------------
__global__ void k_conv1() {
    __shared__ float in_s[32 * 32];   // padded 28+4
    __shared__ float w_s[400];
    int tb = blockIdx.x; int t = tb >> 5, b = tb & 31;
    int tid = threadIdx.x;            // 448 threads
    for (int i = tid; i < 1024; i += blockDim.x) in_s[i] = 0.f;
    __syncthreads();
    const float* src = &g_S0[t * (NB * 784) + b * 784];
    for (int i = tid; i < 784; i += blockDim.x) {
        int y = i / 28, x = i - y * 28;
        in_s[(y + 2) * 32 + (x + 2)] = src[i];
    }
    for (int i = tid; i < 400; i += blockDim.x) w_s[i] = g_W1R[i];
    __syncthreads();

    int ocg = tid / 112; int rem = tid % 112;
    int y = rem >> 2; int x0 = (rem & 3) * 7;
    float acc[4][7];
    #pragma unroll
    for (int o = 0; o < 4; o++)
        #pragma unroll
        for (int xx = 0; xx < 7; xx++) acc[o][xx] = 0.f;

    #pragma unroll
    for (int ky = 0; ky < 5; ky++) {
        float rin[11];
        #pragma unroll
        for (int j = 0; j < 11; j++) rin[j] = in_s[(y + ky) * 32 + x0 + j];
        #pragma unroll
        for (int kx = 0; kx < 5; kx++) {
            float4 w = *(const float4*)&w_s[(ky * 5 + kx) * 16 + ocg * 4];
            #pragma unroll
            for (int xx = 0; xx < 7; xx++) {
                float v = rin[kx + xx];
                acc[0][xx] += w.x * v; acc[1][xx] += w.y * v;
                acc[2][xx] += w.z * v; acc[3][xx] += w.w * v;
            }
        }
    }
    float* dst = &g_U1[t * (NB * 12544) + b * 12544];
    #pragma unroll
    for (int o = 0; o < 4; o++)
        #pragma unroll
        for (int xx = 0; xx < 7; xx++)
            dst[(ocg * 4 + o) * 784 + y * 28 + x0 + xx] = acc[o][xx];
}

// ---------------- generic psp + spike (in place, scan over t) ------------------
__global__ void k_psp(float* u, int plane) {
    int i = blockIdx.x * blockDim.x + threadIdx.x;
    if (i >= plane) return;
    float* p = u + i;
    float s1 = 0.f, s2 = 0.f;
    for (int t = 0; t < T_SIM; t++) {
        float x = p[t * plane];
        s2 = R_DEC * (s2 + s1);        // y[t] uses state at t-1  (eps[0] = 0)
        s1 = R_DEC * s1 + x;
        p[t * plane] = (C_EPS * s2 >= 1.0f) ? 1.0f : 0.0f;
    }
}

// ---------------- 2x2 sum-pool (x1.1) + psp + spike ---------------------------
__global__ void k_pool_psp(const float* __restrict__ sin, float* __restrict__ sout,
                           int Hin, int planeIn, int planeOut, int total) {
    int i = blockIdx.x * blockDim.x + threadIdx.x;
    if (i >= total) return;
    int ho = Hin >> 1;
    int x  = i % ho;
    int y  = (i / ho) % ho;
    int bc = i / (ho * ho);
    int base = bc * Hin * Hin + (2 * y) * Hin + 2 * x;
    float s1 = 0.f, s2 = 0.f;
    for (int t = 0; t < T_SIM; t++) {
        const float* q = sin + t * planeIn + base;
        float u = 1.1f * ((q[0] + q[1]) + (q[Hin] + q[Hin + 1]));
        s2 = R_DEC * (s2 + s1);
        s1 = R_DEC * s1 + u;
        sout[t * planeOut + i] = (C_EPS * s2 >= 1.0f) ? 1.0f : 0.0f;
    }
}

// ---------------- conv2: 16->32ch, 14x14, 5x5 pad2, per (t,b) plane ------------
__global__ void k_conv2() {
    __shared__ float in_s[16 * 18 * 18];   // 5184 floats, padded 14+4
    int tb = blockIdx.x; int t = tb >> 5, b = tb & 31;
    int tid = threadIdx.x;                 // 224 threads
    for (int i = tid; i < 5184; i += blockDim.x) in_s[i] = 0.f;
    __syncthreads();
    const float* src = &g_S1p[t * (NB * 3136) + b * 3136];
    for (int i = tid; i < 3136; i += blockDim.x) {
        int ci = i / 196, r = i - ci * 196;
        int y = r / 14, x = r - y * 14;
        in_s[ci * 324 + (y + 2) * 18 + (x + 2)] = src[i];
    }
    __syncthreads();

    int ocg = tid / 28; int rem = tid % 28;
    int y = rem >> 1; int x0 = (rem & 1) * 7;
    float acc[4][7];
    #pragma unroll
    for (int o = 0; o < 4; o++)
        #pragma unroll
        for (int xx = 0; xx < 7; xx++) acc[o][xx] = 0.f;

    const float4* wp = (const float4*)g_W2R;   // [(ci*25+kq)*8 + ocg]
    #pragma unroll 1
    for (int ci = 0; ci < 16; ci++) {
        #pragma unroll
        for (int ky = 0; ky < 5; ky++) {
            float rin[11];
            #pragma unroll
            for (int j = 0; j < 11; j++) rin[j] = in_s[ci * 324 + (y + ky) * 18 + x0 + j];
            #pragma unroll
            for (int kx = 0; kx < 5; kx++) {
                float4 w = __ldg(&wp[(ci * 25 + ky * 5 + kx) * 8 + ocg]);
                #pragma unroll
                for (int xx = 0; xx < 7; xx++) {
                    float v = rin[kx + xx];
                    acc[0][xx] += w.x * v; acc[1][xx] += w.y * v;
                    acc[2][xx] += w.z * v; acc[3][xx] += w.w * v;
                }
            }
        }
    }
    float* dst = &g_U2[t * (NB * 6272) + b * 6272];
    #pragma unroll
    for (int o = 0; o < 4; o++)
        #pragma unroll
        for (int xx = 0; xx < 7; xx++)
            dst[(ocg * 4 + o) * 196 + y * 14 + x0 + xx] = acc[o][xx];
}

// ---------------- fc1: GEMM  C[3200,410] = S2p[3200,1568] * wf1^T --------------
__global__ void k_dense1(const float* __restrict__ wf1) {
    __shared__ float As[16][64];
    __shared__ float Bs[16][64];
    int n0 = blockIdx.x * 64;
    int m0 = blockIdx.y * 64;
    int tid = threadIdx.x;                 // 256
    int tx = tid & 15, ty = tid >> 4;
    int lm = tid >> 2;                     // 0..63
    int lk = (tid & 3) << 2;               // 0,4,8,12
    float acc[4][4];
    #pragma unroll
    for (int i2 = 0; i2 < 4; i2++)
        #pragma unroll
        for (int j = 0; j < 4; j++) acc[i2][j] = 0.f;

    const float* arow = &g_S2p[(m0 + lm) * 1568 + lk];
    int nrow = n0 + lm;
    const float* brow = (nrow < 410) ? &wf1[nrow * 1568 + lk] : 0;

    for (int kt = 0; kt < 1568; kt += 16) {
        float4 a4 = *(const float4*)(arow + kt);
        float4 b4 = brow ? *(const float4*)(brow + kt) : make_float4(0.f, 0.f, 0.f, 0.f);
        As[lk + 0][lm] = a4.x; As[lk + 1][lm] = a4.y; As[lk + 2][lm] = a4.z; As[lk + 3][lm] = a4.w;
        Bs[lk + 0][lm] = b4.x; Bs[lk + 1][lm] = b4.y; Bs[lk + 2][lm] = b4.z; Bs[lk + 3][lm] = b4.w;
        __syncthreads();
        #pragma unroll
        for (int k = 0; k < 16; k++) {
            float4 av = *(const float4*)&As[k][ty * 4];
            float4 bv = *(const float4*)&Bs[k][tx * 4];
            acc[0][0] += av.x * bv.x; acc[0][1] += av.x * bv.y; acc[0][2] += av.x * bv.z; acc[0][3] += av.x * bv.w;
            acc[1][0] += av.y * bv.x; acc[1][1] += av.y * bv.y; acc[1][2] += av.y * bv.z; acc[1][3] += av.y * bv.w;
            acc[2][0] += av.z * bv.x; acc[2][1] += av.z * bv.y; acc[2][2] += av.z * bv.z; acc[2][3] += av.z * bv.w;
            acc[3][0] += av.w * bv.x; acc[3][1] += av.w * bv.y; acc[3][2] += av.w * bv.z; acc[3][3] += av.w * bv.w;
        }
        __syncthreads();
    }
    #pragma unroll
    for (int i2 = 0; i2 < 4; i2++) {
        int m = m0 + ty * 4 + i2;
        #pragma unroll
        for (int j = 0; j < 4; j++) {
            int n = n0 + tx * 4 + j;
            if (n < 410) g_U3[m * 410 + n] = acc[i2][j];
        }
    }
}

// ---------------- fc2: [3200,10] = S3[3200,410] * wf2^T ------------------------
__global__ void k_dense2(const float* __restrict__ wf2) {
    int i = blockIdx.x * blockDim.x + threadIdx.x;
    if (i >= 32000) return;
    int m = i / 10, o = i - (i / 10) * 10;
    const float* a = &g_U3[m * 410];
    const float* w = &wf2[o * 410];
    float acc = 0.f;
    #pragma unroll 2
    for (int k = 0; k < 410; k++) acc += a[k] * w[k];
    g_U4[m * 10 + o] = acc;
}

// ---------------- final psp + spike + transpose to [b][o][t] -------------------
__global__ void k_final(float* __restrict__ out) {
    int i = threadIdx.x;                   // 320 = b*10+o
    if (i >= 320) return;
    float s1 = 0.f, s2 = 0.f;
    for (int t = 0; t < T_SIM; t++) {
        float x = g_U4[t * 320 + i];
        s2 = R_DEC * (s2 + s1);
        s1 = R_DEC * s1 + x;
        out[i * T_SIM + t] = (C_EPS * s2 >= 1.0f) ? 1.0f : 0.0f;
    }
}

// -------------------------------------------------------------------------------
extern "C" void kernel_launch(void* const* d_in, const int* in_sizes, int n_in,
                              void* d_out, int out_size) {
    const float* img    = (const float*)d_in[0];
    const float* rand_u = (const float*)d_in[1];
    const float* w1     = (const float*)d_in[2];
    const float* w2     = (const float*)d_in[3];
    const float* wf1    = (const float*)d_in[4];
    const float* wf2    = (const float*)d_in[5];
    float* out = (float*)d_out;

    void *pU1, *pU2, *pU3, *pS1p, *pS2p;
    cudaGetSymbolAddress(&pU1,  g_U1);
    cudaGetSymbolAddress(&pU2,  g_U2);
    cudaGetSymbolAddress(&pU3,  g_U3);
    cudaGetSymbolAddress(&pS1p, g_S1p);
    cudaGetSymbolAddress(&pS2p, g_S2p);

    k_encode<<<9800, 256>>>(rand_u, img);
    k_reorder<<<50, 256>>>(w1, w2);

    k_conv1<<<3200, 448>>>();
    k_psp<<<1568, 256>>>((float*)pU1, NB * 16 * 784);                       // -> S1
    k_pool_psp<<<392, 256>>>((const float*)pU1, (float*)pS1p,
                             28, NB * 16 * 784, NB * 16 * 196, NB * 16 * 196);

    k_conv2<<<3200, 224>>>();
    k_psp<<<784, 256>>>((float*)pU2, NB * 32 * 196);                        // -> S2
    k_pool_psp<<<196, 256>>>((const float*)pU2, (float*)pS2p,
                             14, NB * 32 * 196, NB * 1568, NB * 1568);

    dim3 g1(7, 50);
    k_dense1<<<g1, 256>>>(wf1);
    k_psp<<<52, 256>>>((float*)pU3, NB * 410);                              // -> S3

    k_dense2<<<125, 256>>>(wf2);
    k_final<<<1, 320>>>(out);
}

// round 3
// speedup vs baseline: 1.9246x; 1.9246x over previous
#include <cuda_runtime.h>

#define T_SIM 100
#define NB 32
// e^{-1/tau}, tau = 10
#define R_DEC 0.9048374180359595f
// e/tau
#define C_EPS 0.2718281828459045f

// ---------------- scratch (device globals; no allocation allowed) -------------
__device__ float g_S0 [T_SIM * NB * 784];          // spikes in   [t][b][28][28]
__device__ float g_U1 [T_SIM * NB * 16 * 784];     // conv1 raw membrane input
__device__ float g_S1p[T_SIM * NB * 16 * 196];     // fused psp+spike+pool+psp+spike
__device__ float g_U2 [T_SIM * NB * 32 * 196];     // conv2 raw membrane input
__device__ float g_S2p[T_SIM * NB * 1568];         // fused chain out (A matrix of fc1)
__device__ float g_U3 [T_SIM * NB * 410];          // fc1 out -> spikes (in place)
__device__ float g_U4 [T_SIM * NB * 10];           // fc2 out (psp+spike fused in final)
__device__ float g_W1R[400];                        // w1 reordered [kq][oc]
__device__ float g_W2R[12800];                      // w2 reordered [ci*25+kq][oc]

// ---------------- encode: bernoulli spikes + transpose to time-major ----------
__global__ void k_encode(const float* __restrict__ rand_u, const float* __restrict__ img) {
    int i = blockIdx.x * blockDim.x + threadIdx.x;
    if (i >= T_SIM * NB * 784) return;
    int bp = i / T_SIM;                 // (b,y,x) flat
    int t  = i - bp * T_SIM;
    float s = (rand_u[i] < img[bp]) ? 1.0f : 0.0f;
    g_S0[t * (NB * 784) + bp] = s;
}

// ---------------- weight reorder (oc innermost for vector loads) --------------
__global__ void k_reorder(const float* __restrict__ w1, const float* __restrict__ w2) {
    int i = blockIdx.x * blockDim.x + threadIdx.x;
    if (i < 400) {
        int oc = i & 15, kq = i >> 4;
        g_W1R[i] = w1[oc * 25 + kq];
    }
    if (i < 12800) {
        int oc = i & 31, kk = i >> 5;
        int ci = kk / 25, kq = kk % 25;
        g_W2R[i] = w2[(oc * 16 + ci) * 25 + kq];
    }
}

// ---------------- conv1: 1->16ch, 28x28, 5x5 pad2, per (t,b) plane -------------
__global__ void k_conv1() {
    __shared__ float in_s[32 * 32];   // padded 28+4
    __shared__ float w_s[400];
    int tb = blockIdx.x; int t = tb >> 5, b = tb & 31;
    int tid = threadIdx.x;            // 448 threads
    for (int i = tid; i < 1024; i += blockDim.x) in_s[i] = 0.f;
    __syncthreads();
    const float* src = &g_S0[t * (NB * 784) + b * 784];
    for (int i = tid; i < 784; i += blockDim.x) {
        int y = i / 28, x = i - y * 28;
        in_s[(y + 2) * 32 + (x + 2)] = src[i];
    }
    for (int i = tid; i < 400; i += blockDim.x) w_s[i] = g_W1R[i];
    __syncthreads();

    int ocg = tid / 112; int rem = tid % 112;
    int y = rem >> 2; int x0 = (rem & 3) * 7;
    float acc[4][7];
    #pragma unroll
    for (int o = 0; o < 4; o++)
        #pragma unroll
        for (int xx = 0; xx < 7; xx++) acc[o][xx] = 0.f;

    #pragma unroll
    for (int ky = 0; ky < 5; ky++) {
        float rin[11];
        #pragma unroll
        for (int j = 0; j < 11; j++) rin[j] = in_s[(y + ky) * 32 + x0 + j];
        #pragma unroll
        for (int kx = 0; kx < 5; kx++) {
            float4 w = *(const float4*)&w_s[(ky * 5 + kx) * 16 + ocg * 4];
            #pragma unroll
            for (int xx = 0; xx < 7; xx++) {
                float v = rin[kx + xx];
                acc[0][xx] += w.x * v; acc[1][xx] += w.y * v;
                acc[2][xx] += w.z * v; acc[3][xx] += w.w * v;
            }
        }
    }
    float* dst = &g_U1[t * (NB * 12544) + b * 12544];
    #pragma unroll
    for (int o = 0; o < 4; o++)
        #pragma unroll
        for (int xx = 0; xx < 7; xx++)
            dst[(ocg * 4 + o) * 784 + y * 28 + x0 + xx] = acc[o][xx];
}

// ------- fused: psp+spike (full res) -> 2x2 pool(x1.1) -> psp+spike ------------
// One thread per POOLED output pixel. 4 input PSP states + 1 output PSP state
// live in registers; the full-res spike tensor never touches memory.
__global__ void k_fused_pp(const float* __restrict__ uin, float* __restrict__ sout,
                           int Hin, int planeIn, int planeOut, int total) {
    int i = blockIdx.x * blockDim.x + threadIdx.x;
    if (i >= total) return;
    int ho = Hin >> 1;
    int x  = i % ho;
    int y  = (i / ho) % ho;
    int bc = i / (ho * ho);
    const float* base = uin + bc * Hin * Hin + (2 * y) * Hin + 2 * x;

    float a1 = 0.f, a2 = 0.f;   // stream (0,0)
    float b1 = 0.f, b2 = 0.f;   // stream (0,1)
    float c1 = 0.f, c2 = 0.f;   // stream (1,0)
    float d1 = 0.f, d2 = 0.f;   // stream (1,1)
    float o1 = 0.f, o2 = 0.f;   // output psp state

    #pragma unroll 4
    for (int t = 0; t < T_SIM; t++) {
        float2 top = *(const float2*)(base + (size_t)t * planeIn);
        float2 bot = *(const float2*)(base + (size_t)t * planeIn + Hin);

        a2 = R_DEC * (a2 + a1); a1 = R_DEC * a1 + top.x;
        b2 = R_DEC * (b2 + b1); b1 = R_DEC * b1 + top.y;
        c2 = R_DEC * (c2 + c1); c1 = R_DEC * c1 + bot.x;
        d2 = R_DEC * (d2 + d1); d1 = R_DEC * d1 + bot.y;

        float spkA = (C_EPS * a2 >= 1.0f) ? 1.0f : 0.0f;
        float spkB = (C_EPS * b2 >= 1.0f) ? 1.0f : 0.0f;
        float spkC = (C_EPS * c2 >= 1.0f) ? 1.0f : 0.0f;
        float spkD = (C_EPS * d2 >= 1.0f) ? 1.0f : 0.0f;
        float pool = 1.1f * ((spkA + spkB) + (spkC + spkD));

        o2 = R_DEC * (o2 + o1); o1 = R_DEC * o1 + pool;
        sout[(size_t)t * planeOut + i] = (C_EPS * o2 >= 1.0f) ? 1.0f : 0.0f;
    }
}

// ---------------- generic psp + spike (in place, scan over t) ------------------
__global__ void k_psp(float* __restrict__ u, int plane) {
    int i = blockIdx.x * blockDim.x + threadIdx.x;
    if (i >= plane) return;
    float* p = u + i;
    float s1 = 0.f, s2 = 0.f;
    #pragma unroll 4
    for (int t = 0; t < T_SIM; t++) {
        float x = p[(size_t)t * plane];
        s2 = R_DEC * (s2 + s1);        // y[t] uses state at t-1  (eps[0] = 0)
        s1 = R_DEC * s1 + x;
        p[(size_t)t * plane] = (C_EPS * s2 >= 1.0f) ? 1.0f : 0.0f;
    }
}

// ---------------- conv2: 16->32ch, 14x14, 5x5 pad2, per (t,b) plane ------------
__global__ void k_conv2() {
    __shared__ float in_s[16 * 18 * 18];   // 5184 floats, padded 14+4
    int tb = blockIdx.x; int t = tb >> 5, b = tb & 31;
    int tid = threadIdx.x;                 // 224 threads
    for (int i = tid; i < 5184; i += blockDim.x) in_s[i] = 0.f;
    __syncthreads();
    const float* src = &g_S1p[t * (NB * 3136) + b * 3136];
    for (int i = tid; i < 3136; i += blockDim.x) {
        int ci = i / 196, r = i - ci * 196;
        int y = r / 14, x = r - y * 14;
        in_s[ci * 324 + (y + 2) * 18 + (x + 2)] = src[i];
    }
    __syncthreads();

    int ocg = tid / 28; int rem = tid % 28;
    int y = rem >> 1; int x0 = (rem & 1) * 7;
    float acc[4][7];
    #pragma unroll
    for (int o = 0; o < 4; o++)
        #pragma unroll
        for (int xx = 0; xx < 7; xx++) acc[o][xx] = 0.f;

    const float4* wp = (const float4*)g_W2R;   // [(ci*25+kq)*8 + ocg]
    #pragma unroll 1
    for (int ci = 0; ci < 16; ci++) {
        #pragma unroll
        for (int ky = 0; ky < 5; ky++) {
            float rin[11];
            #pragma unroll
            for (int j = 0; j < 11; j++) rin[j] = in_s[ci * 324 + (y + ky) * 18 + x0 + j];
            #pragma unroll
            for (int kx = 0; kx < 5; kx++) {
                float4 w = __ldg(&wp[(ci * 25 + ky * 5 + kx) * 8 + ocg]);
                #pragma unroll
                for (int xx = 0; xx < 7; xx++) {
                    float v = rin[kx + xx];
                    acc[0][xx] += w.x * v; acc[1][xx] += w.y * v;
                    acc[2][xx] += w.z * v; acc[3][xx] += w.w * v;
                }
            }
        }
    }
    float* dst = &g_U2[t * (NB * 6272) + b * 6272];
    #pragma unroll
    for (int o = 0; o < 4; o++)
        #pragma unroll
        for (int xx = 0; xx < 7; xx++)
            dst[(ocg * 4 + o) * 196 + y * 14 + x0 + xx] = acc[o][xx];
}

// ---------------- fc1: GEMM  C[3200,410] = S2p[3200,1568] * wf1^T --------------
__global__ void k_dense1(const float* __restrict__ wf1) {
    __shared__ float As[16][64];
    __shared__ float Bs[16][64];
    int n0 = blockIdx.x * 64;
    int m0 = blockIdx.y * 64;
    int tid = threadIdx.x;                 // 256
    int tx = tid & 15, ty = tid >> 4;
    int lm = tid >> 2;                     // 0..63
    int lk = (tid & 3) << 2;               // 0,4,8,12
    float acc[4][4];
    #pragma unroll
    for (int i2 = 0; i2 < 4; i2++)
        #pragma unroll
        for (int j = 0; j < 4; j++) acc[i2][j] = 0.f;

    const float* arow = &g_S2p[(m0 + lm) * 1568 + lk];
    int nrow = n0 + lm;
    const float* brow = (nrow < 410) ? &wf1[nrow * 1568 + lk] : 0;

    for (int kt = 0; kt < 1568; kt += 16) {
        float4 a4 = *(const float4*)(arow + kt);
        float4 b4 = brow ? *(const float4*)(brow + kt) : make_float4(0.f, 0.f, 0.f, 0.f);
        As[lk + 0][lm] = a4.x; As[lk + 1][lm] = a4.y; As[lk + 2][lm] = a4.z; As[lk + 3][lm] = a4.w;
        Bs[lk + 0][lm] = b4.x; Bs[lk + 1][lm] = b4.y; Bs[lk + 2][lm] = b4.z; Bs[lk + 3][lm] = b4.w;
        __syncthreads();
        #pragma unroll
        for (int k = 0; k < 16; k++) {
            float4 av = *(const float4*)&As[k][ty * 4];
            float4 bv = *(const float4*)&Bs[k][tx * 4];
            acc[0][0] += av.x * bv.x; acc[0][1] += av.x * bv.y; acc[0][2] += av.x * bv.z; acc[0][3] += av.x * bv.w;
            acc[1][0] += av.y * bv.x; acc[1][1] += av.y * bv.y; acc[1][2] += av.y * bv.z; acc[1][3] += av.y * bv.w;
            acc[2][0] += av.z * bv.x; acc[2][1] += av.z * bv.y; acc[2][2] += av.z * bv.z; acc[2][3] += av.z * bv.w;
            acc[3][0] += av.w * bv.x; acc[3][1] += av.w * bv.y; acc[3][2] += av.w * bv.z; acc[3][3] += av.w * bv.w;
        }
        __syncthreads();
    }
    #pragma unroll
    for (int i2 = 0; i2 < 4; i2++) {
        int m = m0 + ty * 4 + i2;
        #pragma unroll
        for (int j = 0; j < 4; j++) {
            int n = n0 + tx * 4 + j;
            if (n < 410) g_U3[m * 410 + n] = acc[i2][j];
        }
    }
}

// ---------------- fc2: [3200,10] = S3[3200,410] * wf2^T ------------------------
__global__ void k_dense2(const float* __restrict__ wf2) {
    int i = blockIdx.x * blockDim.x + threadIdx.x;
    if (i >= 32000) return;
    int m = i / 10, o = i - (i / 10) * 10;
    const float* a = &g_U3[m * 410];
    const float* w = &wf2[o * 410];
    float acc = 0.f;
    #pragma unroll 2
    for (int k = 0; k < 410; k++) acc += a[k] * w[k];
    g_U4[m * 10 + o] = acc;
}

// ---------------- final psp + spike + transpose to [b][o][t] -------------------
__global__ void k_final(float* __restrict__ out) {
    int i = threadIdx.x;                   // 320 = b*10+o
    if (i >= 320) return;
    float s1 = 0.f, s2 = 0.f;
    #pragma unroll 4
    for (int t = 0; t < T_SIM; t++) {
        float x = g_U4[t * 320 + i];
        s2 = R_DEC * (s2 + s1);
        s1 = R_DEC * s1 + x;
        out[i * T_SIM + t] = (C_EPS * s2 >= 1.0f) ? 1.0f : 0.0f;
    }
}

// -------------------------------------------------------------------------------
extern "C" void kernel_launch(void* const* d_in, const int* in_sizes, int n_in,
                              void* d_out, int out_size) {
    const float* img    = (const float*)d_in[0];
    const float* rand_u = (const float*)d_in[1];
    const float* w1     = (const float*)d_in[2];
    const float* w2     = (const float*)d_in[3];
    const float* wf1    = (const float*)d_in[4];
    const float* wf2    = (const float*)d_in[5];
    float* out = (float*)d_out;

    void *pU1, *pU2, *pU3, *pS1p, *pS2p;
    cudaGetSymbolAddress(&pU1,  g_U1);
    cudaGetSymbolAddress(&pU2,  g_U2);
    cudaGetSymbolAddress(&pU3,  g_U3);
    cudaGetSymbolAddress(&pS1p, g_S1p);
    cudaGetSymbolAddress(&pS2p, g_S2p);

    k_encode<<<9800, 256>>>(rand_u, img);
    k_reorder<<<50, 256>>>(w1, w2);

    k_conv1<<<3200, 448>>>();
    // fused psp+spike+pool+psp+spike, layer 1: U1[.,16,28,28] -> S1p[.,16,14,14]
    k_fused_pp<<<392, 256>>>((const float*)pU1, (float*)pS1p,
                             28, NB * 16 * 784, NB * 16 * 196, NB * 16 * 196);

    k_conv2<<<3200, 224>>>();
    // fused chain, layer 2: U2[.,32,14,14] -> S2p[.,32,7,7]
    k_fused_pp<<<196, 256>>>((const float*)pU2, (float*)pS2p,
                             14, NB * 32 * 196, NB * 1568, NB * 1568);

    dim3 g1(7, 50);
    k_dense1<<<g1, 256>>>(wf1);
    k_psp<<<52, 256>>>((float*)pU3, NB * 410);                              // -> S3

    k_dense2<<<125, 256>>>(wf2);
    k_final<<<1, 320>>>(out);
}